// round 4
// baseline (speedup 1.0000x reference)
#include <cuda_runtime.h>
#include <math.h>

#define N_ROWS 8192
#define M_ROWS 8192
#define D      512

#define BM 64
#define BN 256
#define KT 32
#define XS_PITCH 65
#define FS_PITCH 258
#define SMEM_BYTES (D*XS_PITCH*4 + KT*FS_PITCH*4)

// Scratch (device globals: no allocation allowed)
__device__ float g_fmu[M_ROWS * D];
__device__ float g_fsq[M_ROWS];
__device__ float g_xsq[N_ROWS];
__device__ float g_lse[N_ROWS];

typedef unsigned long long u64;

__device__ __forceinline__ u64 pack2(float a, float b) {
    u64 r;
    asm("mov.b64 %0, {%1, %2};" : "=l"(r) : "r"(__float_as_uint(a)), "r"(__float_as_uint(b)));
    return r;
}
__device__ __forceinline__ void unpack2(u64 v, float& a, float& b) {
    unsigned int lo, hi;
    asm("mov.b64 {%0, %1}, %2;" : "=r"(lo), "=r"(hi) : "l"(v));
    a = __uint_as_float(lo);
    b = __uint_as_float(hi);
}
__device__ __forceinline__ void fma2(u64& d, u64 a, u64 b) {
    asm("fma.rn.f32x2 %0, %1, %2, %3;" : "=l"(d) : "l"(a), "l"(b), "l"(d));
}

// ---------------------------------------------------------------------------
// Kernel 1: f_mu = tanh(mu @ W^T + b)   (M x Dout, K = D_in = 512)
// grid = (M/BM, Dout/BN) = (128, 2), block = 256
// ---------------------------------------------------------------------------
__global__ __launch_bounds__(256, 1)
void fmu_kernel(const float* __restrict__ mu, const float* __restrict__ W,
                const float* __restrict__ b) {
    extern __shared__ float sm[];
    float* xs = sm;                  // [D][XS_PITCH]  mu-block transposed
    float* fs = sm + D * XS_PITCH;   // [KT][FS_PITCH] W-chunk transposed

    const int tid = threadIdx.x;
    const int tx = tid & 31, ty = tid >> 5;
    const int row0 = blockIdx.x * BM;
    const int cbase = blockIdx.y * BN;

    // load mu block (64 x 512) transposed into smem
    const float4* xsrc = (const float4*)mu + (size_t)row0 * (D / 4);
    #pragma unroll
    for (int it = 0; it < (BM * D / 4) / 256; ++it) {
        int v = tid + it * 256;
        int row = v >> 7;        // 128 float4 per row
        int c4 = v & 127;
        float4 val = xsrc[row * (D / 4) + c4];
        int k = c4 << 2;
        xs[(k + 0) * XS_PITCH + row] = val.x;
        xs[(k + 1) * XS_PITCH + row] = val.y;
        xs[(k + 2) * XS_PITCH + row] = val.z;
        xs[(k + 3) * XS_PITCH + row] = val.w;
    }
    __syncthreads();

    u64 acc[8][4];
    #pragma unroll
    for (int i = 0; i < 8; ++i)
        #pragma unroll
        for (int jj = 0; jj < 4; ++jj) acc[i][jj] = 0ULL;

    const int rbase = ty * 8;
    const float* fbase = W + (size_t)cbase * D;

    float4 pf[8];
    #pragma unroll
    for (int q = 0; q < 8; ++q) {
        int v = tid + q * 256;
        int col = v >> 3, kq = v & 7;
        pf[q] = ((const float4*)fbase)[col * (D / 4) + kq];
    }

    for (int kc = 0; kc < D / KT; ++kc) {
        #pragma unroll
        for (int q = 0; q < 8; ++q) {
            int v = tid + q * 256;
            int col = v >> 3, kq = v & 7;
            fs[(4 * kq + 0) * FS_PITCH + col] = pf[q].x;
            fs[(4 * kq + 1) * FS_PITCH + col] = pf[q].y;
            fs[(4 * kq + 2) * FS_PITCH + col] = pf[q].z;
            fs[(4 * kq + 3) * FS_PITCH + col] = pf[q].w;
        }
        __syncthreads();
        if (kc + 1 < D / KT) {
            #pragma unroll
            for (int q = 0; q < 8; ++q) {
                int v = tid + q * 256;
                int col = v >> 3, kq = v & 7;
                pf[q] = ((const float4*)fbase)[col * (D / 4) + (kc + 1) * (KT / 4) + kq];
            }
        }
        #pragma unroll 4
        for (int kk = 0; kk < KT; ++kk) {
            int k = kc * KT + kk;
            u64 b2[4];
            #pragma unroll
            for (int jj = 0; jj < 4; ++jj)
                b2[jj] = *(const u64*)&fs[kk * FS_PITCH + jj * 64 + (tx << 1)];
            #pragma unroll
            for (int i = 0; i < 8; ++i) {
                float a = xs[k * XS_PITCH + rbase + i];
                u64 a2 = pack2(a, a);
                #pragma unroll
                for (int jj = 0; jj < 4; ++jj) fma2(acc[i][jj], a2, b2[jj]);
            }
        }
        __syncthreads();
    }

    // epilogue: tanh(acc + b) -> g_fmu
    #pragma unroll
    for (int i = 0; i < 8; ++i) {
        int row = row0 + rbase + i;
        #pragma unroll
        for (int jj = 0; jj < 4; ++jj) {
            int col0 = cbase + jj * 64 + (tx << 1);
            float c0, c1;
            unpack2(acc[i][jj], c0, c1);
            float2 o;
            o.x = tanhf(c0 + b[col0]);
            o.y = tanhf(c1 + b[col0 + 1]);
            *(float2*)&g_fmu[(size_t)row * D + col0] = o;
        }
    }
}

// ---------------------------------------------------------------------------
// Kernel 2: row sums of squares for x (-> g_xsq) and f_mu (-> g_fsq).
// one warp per row; 16384 warps -> 2048 blocks of 256 threads
// ---------------------------------------------------------------------------
__global__ void rowsq_kernel(const float* __restrict__ x) {
    int w = (blockIdx.x * blockDim.x + threadIdx.x) >> 5;
    int lane = threadIdx.x & 31;
    const float* src;
    float* dst;
    int row;
    if (w < N_ROWS) { src = x; dst = g_xsq; row = w; }
    else            { src = g_fmu; dst = g_fsq; row = w - N_ROWS; }
    const float4* p = (const float4*)(src + (size_t)row * D);
    float s = 0.f;
    #pragma unroll
    for (int i = lane; i < D / 4; i += 32) {
        float4 v = p[i];
        s += v.x * v.x + v.y * v.y + v.z * v.z + v.w * v.w;
    }
    #pragma unroll
    for (int off = 16; off; off >>= 1) s += __shfl_xor_sync(0xffffffffu, s, off);
    if (lane == 0) dst[row] = s;
}

// ---------------------------------------------------------------------------
// Kernel 3: fused cross-GEMM + online logsumexp.
// grid = N/BM = 128, block = 256
// ---------------------------------------------------------------------------
__global__ __launch_bounds__(256, 1)
void lse_kernel(const float* __restrict__ x) {
    extern __shared__ float sm[];
    float* xs = sm;                  // [D][XS_PITCH]
    float* fs = sm + D * XS_PITCH;   // [KT][FS_PITCH]

    const int tid = threadIdx.x;
    const int tx = tid & 31, ty = tid >> 5;
    const int row0 = blockIdx.x * BM;

    const float4* xsrc = (const float4*)x + (size_t)row0 * (D / 4);
    #pragma unroll
    for (int it = 0; it < (BM * D / 4) / 256; ++it) {
        int v = tid + it * 256;
        int row = v >> 7;
        int c4 = v & 127;
        float4 val = xsrc[row * (D / 4) + c4];
        int k = c4 << 2;
        xs[(k + 0) * XS_PITCH + row] = val.x;
        xs[(k + 1) * XS_PITCH + row] = val.y;
        xs[(k + 2) * XS_PITCH + row] = val.z;
        xs[(k + 3) * XS_PITCH + row] = val.w;
    }
    __syncthreads();

    float run_mx[8], run_s[8];
    #pragma unroll
    for (int i = 0; i < 8; ++i) { run_mx[i] = -INFINITY; run_s[i] = 0.f; }

    const int rbase = ty * 8;

    for (int ct = 0; ct < M_ROWS / BN; ++ct) {
        u64 acc[8][4];
        #pragma unroll
        for (int i = 0; i < 8; ++i)
            #pragma unroll
            for (int jj = 0; jj < 4; ++jj) acc[i][jj] = 0ULL;

        const float* fbase = g_fmu + (size_t)(ct * BN) * D;

        float4 pf[8];
        #pragma unroll
        for (int q = 0; q < 8; ++q) {
            int v = tid + q * 256;
            int col = v >> 3, kq = v & 7;
            pf[q] = ((const float4*)fbase)[col * (D / 4) + kq];
        }

        for (int kc = 0; kc < D / KT; ++kc) {
            #pragma unroll
            for (int q = 0; q < 8; ++q) {
                int v = tid + q * 256;
                int col = v >> 3, kq = v & 7;
                fs[(4 * kq + 0) * FS_PITCH + col] = pf[q].x;
                fs[(4 * kq + 1) * FS_PITCH + col] = pf[q].y;
                fs[(4 * kq + 2) * FS_PITCH + col] = pf[q].z;
                fs[(4 * kq + 3) * FS_PITCH + col] = pf[q].w;
            }
            __syncthreads();
            if (kc + 1 < D / KT) {
                #pragma unroll
                for (int q = 0; q < 8; ++q) {
                    int v = tid + q * 256;
                    int col = v >> 3, kq = v & 7;
                    pf[q] = ((const float4*)fbase)[col * (D / 4) + (kc + 1) * (KT / 4) + kq];
                }
            }
            #pragma unroll 4
            for (int kk = 0; kk < KT; ++kk) {
                int k = kc * KT + kk;
                u64 b2[4];
                #pragma unroll
                for (int jj = 0; jj < 4; ++jj)
                    b2[jj] = *(const u64*)&fs[kk * FS_PITCH + jj * 64 + (tx << 1)];
                #pragma unroll
                for (int i = 0; i < 8; ++i) {
                    float a = xs[k * XS_PITCH + rbase + i];
                    u64 a2 = pack2(a, a);
                    #pragma unroll
                    for (int jj = 0; jj < 4; ++jj) fma2(acc[i][jj], a2, b2[jj]);
                }
            }
            __syncthreads();
        }

        // epilogue: m = cross - 0.5*f_sq ; per-thread online logsumexp
        const int cbase = ct * BN;
        float fsq0[4], fsq1[4];
        #pragma unroll
        for (int jj = 0; jj < 4; ++jj) {
            float2 t = *(const float2*)&g_fsq[cbase + jj * 64 + (tx << 1)];
            fsq0[jj] = t.x; fsq1[jj] = t.y;
        }
        #pragma unroll
        for (int i = 0; i < 8; ++i) {
            float m[8];
            #pragma unroll
            for (int jj = 0; jj < 4; ++jj) {
                float c0, c1;
                unpack2(acc[i][jj], c0, c1);
                m[2 * jj]     = c0 - 0.5f * fsq0[jj];
                m[2 * jj + 1] = c1 - 0.5f * fsq1[jj];
            }
            float tm = m[0];
            #pragma unroll
            for (int j = 1; j < 8; ++j) tm = fmaxf(tm, m[j]);
            float nm = fmaxf(run_mx[i], tm);
            float ssum = 0.f;
            #pragma unroll
            for (int j = 0; j < 8; ++j) ssum += __expf(m[j] - nm);
            run_s[i] = run_s[i] * __expf(run_mx[i] - nm) + ssum;
            run_mx[i] = nm;
        }
    }

    // merge (max, sumexp) across the 32 lanes; each warp owns 8 unique rows
    #pragma unroll
    for (int i = 0; i < 8; ++i) {
        float mx = run_mx[i], s = run_s[i];
        #pragma unroll
        for (int off = 16; off; off >>= 1) {
            float omx = __shfl_xor_sync(0xffffffffu, mx, off);
            float os  = __shfl_xor_sync(0xffffffffu, s, off);
            float nm = fmaxf(mx, omx);
            s = s * __expf(mx - nm) + os * __expf(omx - nm);
            mx = nm;
        }
        if (tx == 0) {
            int row = row0 + rbase + i;
            g_lse[row] = mx + __logf(s) - 0.5f * g_xsq[row];
        }
    }
}

// ---------------------------------------------------------------------------
// Kernel 4: out = -sum(g_lse)   (deterministic tree reduction)
// ---------------------------------------------------------------------------
__global__ void reduce_kernel(float* __restrict__ out) {
    __shared__ float sh[256];
    float s = 0.f;
    for (int i = threadIdx.x; i < N_ROWS; i += 256) s += g_lse[i];
    sh[threadIdx.x] = s;
    __syncthreads();
    for (int st = 128; st; st >>= 1) {
        if (threadIdx.x < st) sh[threadIdx.x] += sh[threadIdx.x + st];
        __syncthreads();
    }
    if (threadIdx.x == 0) out[0] = -sh[0];
}

extern "C" void kernel_launch(void* const* d_in, const int* in_sizes, int n_in,
                              void* d_out, int out_size) {
    const float* x  = (const float*)d_in[0];
    const float* mu = (const float*)d_in[1];
    const float* W  = (const float*)d_in[2];
    const float* b  = (const float*)d_in[3];
    float* out = (float*)d_out;

    cudaFuncSetAttribute(fmu_kernel, cudaFuncAttributeMaxDynamicSharedMemorySize, SMEM_BYTES);
    cudaFuncSetAttribute(lse_kernel, cudaFuncAttributeMaxDynamicSharedMemorySize, SMEM_BYTES);

    fmu_kernel<<<dim3(M_ROWS / BM, D / BN), 256, SMEM_BYTES>>>(mu, W, b);
    rowsq_kernel<<<2048, 256>>>(x);   // 16384 warps: one per row of x and f_mu
    lse_kernel<<<N_ROWS / BM, 256, SMEM_BYTES>>>(x);
    reduce_kernel<<<1, 256>>>(out);
}

// round 6
// speedup vs baseline: 2.7728x; 2.7728x over previous
#include <cuda_runtime.h>
#include <math.h>
#include <stdint.h>

#define N_ROWS 8192
#define M_ROWS 8192
#define D      512

// ------------------------- SIMT fmu kernel config --------------------------
#define BM 64
#define BN 256
#define KT 32
#define XS_PITCH 65
#define FS_PITCH 258
#define SMEM_BYTES (D*XS_PITCH*4 + KT*FS_PITCH*4)

// ------------------------- mma LSE kernel config ---------------------------
#define MMA_BM 128             // x rows per CTA
#define MMA_BN 128             // f cols per chunk
#define MMA_KT 32              // K per stage
#define NSLICE 8               // M split into 8 slices of 1024 cols
#define NCHUNK 8               // chunks per slice (1024/128)
#define NKST   16              // K stages (512/32)
#define PITCH  36              // smem row pitch in floats (conflict-free)
#define PITCHB (PITCH*4)       // 144 bytes
#define STAGEB ((MMA_BM + MMA_BN) * PITCHB)   // 36864 B per stage
#define MMA_SMEM (2 * STAGEB)                  // 73728 B
#define NPART (NSLICE * 4)     // 32 LSE partials per row (4 warp-cols)

// Scratch (device globals: no allocation allowed)
__device__ float g_fmu[M_ROWS * D];   // tanh output, tf32-rounded
__device__ float g_xc [N_ROWS * D];   // x, tf32-rounded
__device__ float g_fsq[M_ROWS];
__device__ float g_xsq[N_ROWS];
__device__ float g_pmx[NPART * N_ROWS];
__device__ float g_ps [NPART * N_ROWS];
__device__ float g_lse[N_ROWS];

typedef unsigned long long u64;

// ------------------------------ helpers ------------------------------------
__device__ __forceinline__ uint32_t smem_u32(const void* p) {
    uint32_t a;
    asm("{ .reg .u64 t; cvta.to.shared.u64 t, %1; cvt.u32.u64 %0, t; }" : "=r"(a) : "l"(p));
    return a;
}
__device__ __forceinline__ void cp16(uint32_t dst, const void* src) {
    asm volatile("cp.async.cg.shared.global [%0], [%1], 16;" :: "r"(dst), "l"(src) : "memory");
}
__device__ __forceinline__ void cp_commit() {
    asm volatile("cp.async.commit_group;" ::: "memory");
}
template <int N>
__device__ __forceinline__ void cp_wait() {
    asm volatile("cp.async.wait_group %0;" :: "n"(N) : "memory");
}
__device__ __forceinline__ void mma_tf32(float* c, const uint32_t* a, const uint32_t* b) {
    asm volatile(
        "mma.sync.aligned.m16n8k8.row.col.f32.tf32.tf32.f32 "
        "{%0,%1,%2,%3}, {%4,%5,%6,%7}, {%8,%9}, {%0,%1,%2,%3};"
        : "+f"(c[0]), "+f"(c[1]), "+f"(c[2]), "+f"(c[3])
        : "r"(a[0]), "r"(a[1]), "r"(a[2]), "r"(a[3]), "r"(b[0]), "r"(b[1]));
}
__device__ __forceinline__ float tf32_rna(float v) {
    uint32_t u = __float_as_uint(v);
    asm("cvt.rna.tf32.f32 %0, %0;" : "+r"(u));
    return __uint_as_float(u);
}
__device__ __forceinline__ u64 pack2(float a, float b) {
    u64 r;
    asm("mov.b64 %0, {%1, %2};" : "=l"(r) : "r"(__float_as_uint(a)), "r"(__float_as_uint(b)));
    return r;
}
__device__ __forceinline__ void unpack2(u64 v, float& a, float& b) {
    unsigned int lo, hi;
    asm("mov.b64 {%0, %1}, %2;" : "=r"(lo), "=r"(hi) : "l"(v));
    a = __uint_as_float(lo);
    b = __uint_as_float(hi);
}
__device__ __forceinline__ void fma2(u64& d, u64 a, u64 b) {
    asm("fma.rn.f32x2 %0, %1, %2, %3;" : "=l"(d) : "l"(a), "l"(b), "l"(d));
}

// ---------------------------------------------------------------------------
// Kernel 1: f_mu = tanh(mu @ W^T + b), stored tf32-rounded. (fp32 SIMT GEMM)
// grid (128, 2), block 256
// ---------------------------------------------------------------------------
__global__ __launch_bounds__(256, 1)
void fmu_kernel(const float* __restrict__ mu, const float* __restrict__ W,
                const float* __restrict__ b) {
    extern __shared__ float sm[];
    float* xs = sm;
    float* fs = sm + D * XS_PITCH;

    const int tid = threadIdx.x;
    const int tx = tid & 31, ty = tid >> 5;
    const int row0 = blockIdx.x * BM;
    const int cbase = blockIdx.y * BN;

    const float4* xsrc = (const float4*)mu + (size_t)row0 * (D / 4);
    #pragma unroll
    for (int it = 0; it < (BM * D / 4) / 256; ++it) {
        int v = tid + it * 256;
        int row = v >> 7, c4 = v & 127;
        float4 val = xsrc[row * (D / 4) + c4];
        int k = c4 << 2;
        xs[(k + 0) * XS_PITCH + row] = val.x;
        xs[(k + 1) * XS_PITCH + row] = val.y;
        xs[(k + 2) * XS_PITCH + row] = val.z;
        xs[(k + 3) * XS_PITCH + row] = val.w;
    }
    __syncthreads();

    u64 acc[8][4];
    #pragma unroll
    for (int i = 0; i < 8; ++i)
        #pragma unroll
        for (int jj = 0; jj < 4; ++jj) acc[i][jj] = 0ULL;

    const int rbase = ty * 8;
    const float* fbase = W + (size_t)cbase * D;

    float4 pf[8];
    #pragma unroll
    for (int q = 0; q < 8; ++q) {
        int v = tid + q * 256;
        int col = v >> 3, kq = v & 7;
        pf[q] = ((const float4*)fbase)[col * (D / 4) + kq];
    }

    for (int kc = 0; kc < D / KT; ++kc) {
        #pragma unroll
        for (int q = 0; q < 8; ++q) {
            int v = tid + q * 256;
            int col = v >> 3, kq = v & 7;
            fs[(4 * kq + 0) * FS_PITCH + col] = pf[q].x;
            fs[(4 * kq + 1) * FS_PITCH + col] = pf[q].y;
            fs[(4 * kq + 2) * FS_PITCH + col] = pf[q].z;
            fs[(4 * kq + 3) * FS_PITCH + col] = pf[q].w;
        }
        __syncthreads();
        if (kc + 1 < D / KT) {
            #pragma unroll
            for (int q = 0; q < 8; ++q) {
                int v = tid + q * 256;
                int col = v >> 3, kq = v & 7;
                pf[q] = ((const float4*)fbase)[col * (D / 4) + (kc + 1) * (KT / 4) + kq];
            }
        }
        #pragma unroll 4
        for (int kk = 0; kk < KT; ++kk) {
            int k = kc * KT + kk;
            u64 b2[4];
            #pragma unroll
            for (int jj = 0; jj < 4; ++jj)
                b2[jj] = *(const u64*)&fs[kk * FS_PITCH + jj * 64 + (tx << 1)];
            #pragma unroll
            for (int i = 0; i < 8; ++i) {
                float a = xs[k * XS_PITCH + rbase + i];
                u64 a2 = pack2(a, a);
                #pragma unroll
                for (int jj = 0; jj < 4; ++jj) fma2(acc[i][jj], a2, b2[jj]);
            }
        }
        __syncthreads();
    }

    #pragma unroll
    for (int i = 0; i < 8; ++i) {
        int row = row0 + rbase + i;
        #pragma unroll
        for (int jj = 0; jj < 4; ++jj) {
            int col0 = cbase + jj * 64 + (tx << 1);
            float c0, c1;
            unpack2(acc[i][jj], c0, c1);
            float2 o;
            o.x = tf32_rna(tanhf(c0 + b[col0]));
            o.y = tf32_rna(tanhf(c1 + b[col0 + 1]));
            *(float2*)&g_fmu[(size_t)row * D + col0] = o;
        }
    }
}

// ---------------------------------------------------------------------------
// Kernel 2: row sums of squares (g_xsq from ORIGINAL x, g_fsq from rounded
// g_fmu), plus tf32-rounded copy of x into g_xc. one warp per row.
// ---------------------------------------------------------------------------
__global__ void rowsq_kernel(const float* __restrict__ x) {
    int w = (blockIdx.x * blockDim.x + threadIdx.x) >> 5;
    int lane = threadIdx.x & 31;
    bool is_x = (w < N_ROWS);
    int row = is_x ? w : (w - N_ROWS);
    const float* src = is_x ? x : g_fmu;
    float* dst = is_x ? g_xsq : g_fsq;
    const float4* p = (const float4*)(src + (size_t)row * D);
    float s = 0.f;
    #pragma unroll
    for (int i = lane; i < D / 4; i += 32) {
        float4 v = p[i];
        s += v.x * v.x + v.y * v.y + v.z * v.z + v.w * v.w;
        if (is_x) {
            float4 r4;
            r4.x = tf32_rna(v.x); r4.y = tf32_rna(v.y);
            r4.z = tf32_rna(v.z); r4.w = tf32_rna(v.w);
            ((float4*)(g_xc + (size_t)row * D))[i] = r4;
        }
    }
    #pragma unroll
    for (int off = 16; off; off >>= 1) s += __shfl_xor_sync(0xffffffffu, s, off);
    if (lane == 0) dst[row] = s;
}

// ---------------------------------------------------------------------------
// Kernel 3: mma.sync (tf32) cross-GEMM fused with online logsumexp.
// grid (64 row-blocks, 8 M-slices), block 256 (8 warps, 2 warprows x 4 warpcols)
// CTA: 128 rows x 1024 cols (8 chunks of 128), K=512 in 16 stages of 32.
// ---------------------------------------------------------------------------
__global__ __launch_bounds__(256)
void lse_mma_kernel() {
    extern __shared__ char smraw[];
    const uint32_t smb = smem_u32(smraw);

    const int tid = threadIdx.x;
    const int wid = tid >> 5;
    const int lane = tid & 31;
    const int lr = lane >> 2;          // 0..7
    const int lc = lane & 3;           // 0..3
    const int warprow = wid >> 2;      // 0..1
    const int warpcol = wid & 3;       // 0..3

    const int row0 = blockIdx.x * MMA_BM;
    const int slice = blockIdx.y;
    const int col_slice0 = slice * (MMA_BN * NCHUNK);

    const char* gA0 = (const char*)g_xc + (size_t)row0 * (D * 4);
    const char* gB0 = (const char*)g_fmu + (size_t)col_slice0 * (D * 4);

    // stage loader: 8 cp16 per thread (4 for A tile, 4 for B tile)
    auto load_stage = [&](int s) {
        int kc = s & (NKST - 1);
        int ch = s >> 4;
        uint32_t bufA = smb + (s & 1) * STAGEB;
        uint32_t bufB = bufA + MMA_BM * PITCHB;
        const char* srcA = gA0 + (size_t)kc * (MMA_KT * 4);
        const char* srcB = gB0 + (size_t)ch * (MMA_BN * D * 4) + (size_t)kc * (MMA_KT * 4);
        #pragma unroll
        for (int q = 0; q < 4; ++q) {
            int idx = tid + q * 256;
            int row = idx >> 3, s8 = idx & 7;
            cp16(bufA + row * PITCHB + s8 * 16, srcA + (size_t)row * (D * 4) + s8 * 16);
        }
        #pragma unroll
        for (int q = 0; q < 4; ++q) {
            int idx = tid + q * 256;
            int row = idx >> 3, s8 = idx & 7;
            cp16(bufB + row * PITCHB + s8 * 16, srcB + (size_t)row * (D * 4) + s8 * 16);
        }
        cp_commit();
    };

    float acc[4][4][4];
    #pragma unroll
    for (int mt = 0; mt < 4; ++mt)
        #pragma unroll
        for (int nt = 0; nt < 4; ++nt)
            #pragma unroll
            for (int r = 0; r < 4; ++r) acc[mt][nt][r] = 0.f;

    float run_mx[8], run_s[8];
    #pragma unroll
    for (int i = 0; i < 8; ++i) { run_mx[i] = -INFINITY; run_s[i] = 0.f; }

    const int TOT = NCHUNK * NKST;     // 128 stages
    load_stage(0);

    for (int s = 0; s < TOT; ++s) {
        if (s + 1 < TOT) { load_stage(s + 1); cp_wait<1>(); }
        else             { cp_wait<0>(); }
        __syncthreads();

        const float* As = (const float*)(smraw + (s & 1) * STAGEB);
        const float* Bs = As + MMA_BM * PITCH;

        #pragma unroll
        for (int k8 = 0; k8 < 4; ++k8) {
            const int kb = k8 * 8;
            uint32_t a[4][4], b[4][2];
            #pragma unroll
            for (int mt = 0; mt < 4; ++mt) {
                int r0 = warprow * 64 + mt * 16 + lr;
                a[mt][0] = __float_as_uint(As[(r0    ) * PITCH + kb + lc    ]);
                a[mt][1] = __float_as_uint(As[(r0 + 8) * PITCH + kb + lc    ]);
                a[mt][2] = __float_as_uint(As[(r0    ) * PITCH + kb + lc + 4]);
                a[mt][3] = __float_as_uint(As[(r0 + 8) * PITCH + kb + lc + 4]);
            }
            #pragma unroll
            for (int nt = 0; nt < 4; ++nt) {
                int c0 = warpcol * 32 + nt * 8 + lr;
                b[nt][0] = __float_as_uint(Bs[c0 * PITCH + kb + lc    ]);
                b[nt][1] = __float_as_uint(Bs[c0 * PITCH + kb + lc + 4]);
            }
            #pragma unroll
            for (int mt = 0; mt < 4; ++mt)
                #pragma unroll
                for (int nt = 0; nt < 4; ++nt)
                    mma_tf32(acc[mt][nt], a[mt], b[nt]);
        }

        if ((s & (NKST - 1)) == NKST - 1) {
            // chunk finished: epilogue (register-only, no smem)
            int ch = s >> 4;
            const int colg0 = col_slice0 + ch * MMA_BN + warpcol * 32;
            float fq[4][2];
            #pragma unroll
            for (int nt = 0; nt < 4; ++nt) {
                int cg = colg0 + nt * 8 + lc * 2;
                fq[nt][0] = __ldg(&g_fsq[cg]);
                fq[nt][1] = __ldg(&g_fsq[cg + 1]);
            }
            #pragma unroll
            for (int mt = 0; mt < 4; ++mt) {
                #pragma unroll
                for (int rh = 0; rh < 2; ++rh) {
                    const int si = mt * 2 + rh;
                    float mv[8];
                    #pragma unroll
                    for (int nt = 0; nt < 4; ++nt) {
                        mv[2 * nt]     = acc[mt][nt][rh * 2]     - 0.5f * fq[nt][0];
                        mv[2 * nt + 1] = acc[mt][nt][rh * 2 + 1] - 0.5f * fq[nt][1];
                    }
                    float tm = mv[0];
                    #pragma unroll
                    for (int j = 1; j < 8; ++j) tm = fmaxf(tm, mv[j]);
                    float nm = fmaxf(run_mx[si], tm);
                    float ss = 0.f;
                    #pragma unroll
                    for (int j = 0; j < 8; ++j) ss += __expf(mv[j] - nm);
                    run_s[si] = run_s[si] * __expf(run_mx[si] - nm) + ss;
                    run_mx[si] = nm;
                }
            }
            #pragma unroll
            for (int mt = 0; mt < 4; ++mt)
                #pragma unroll
                for (int nt = 0; nt < 4; ++nt)
                    #pragma unroll
                    for (int r = 0; r < 4; ++r) acc[mt][nt][r] = 0.f;
        }
        __syncthreads();
    }

    // merge (mx,s) across the 4 lanes of each quad (same row, different cols)
    #pragma unroll
    for (int i = 0; i < 8; ++i) {
        float mx = run_mx[i], ss = run_s[i];
        #pragma unroll
        for (int off = 1; off <= 2; off <<= 1) {
            float omx = __shfl_xor_sync(0xffffffffu, mx, off);
            float os  = __shfl_xor_sync(0xffffffffu, ss, off);
            float nm = fmaxf(mx, omx);
            ss = ss * __expf(mx - nm) + os * __expf(omx - nm);
            mx = nm;
        }
        if (lc == 0) {
            int row = row0 + warprow * 64 + (i >> 1) * 16 + lr + (i & 1) * 8;
            int p = slice * 4 + warpcol;
            g_pmx[(size_t)p * N_ROWS + row] = mx;
            g_ps [(size_t)p * N_ROWS + row] = ss;
        }
    }
}

// ---------------------------------------------------------------------------
// Kernel 4: merge NPART partials per row -> g_lse. grid 32 x 256.
// ---------------------------------------------------------------------------
__global__ void finalize_kernel() {
    int row = blockIdx.x * blockDim.x + threadIdx.x;
    float mx = -INFINITY, s = 0.f;
    #pragma unroll 4
    for (int p = 0; p < NPART; ++p) {
        float omx = g_pmx[(size_t)p * N_ROWS + row];
        float os  = g_ps [(size_t)p * N_ROWS + row];
        float nm = fmaxf(mx, omx);
        s = s * __expf(mx - nm) + os * __expf(omx - nm);
        mx = nm;
    }
    g_lse[row] = mx + __logf(s) - 0.5f * g_xsq[row];
}

// ---------------------------------------------------------------------------
// Kernel 5: out = -sum(g_lse)  (deterministic tree reduction)
// ---------------------------------------------------------------------------
__global__ void reduce_kernel(float* __restrict__ out) {
    __shared__ float sh[256];
    float s = 0.f;
    for (int i = threadIdx.x; i < N_ROWS; i += 256) s += g_lse[i];
    sh[threadIdx.x] = s;
    __syncthreads();
    for (int st = 128; st; st >>= 1) {
        if (threadIdx.x < st) sh[threadIdx.x] += sh[threadIdx.x + st];
        __syncthreads();
    }
    if (threadIdx.x == 0) out[0] = -sh[0];
}

extern "C" void kernel_launch(void* const* d_in, const int* in_sizes, int n_in,
                              void* d_out, int out_size) {
    const float* x  = (const float*)d_in[0];
    const float* mu = (const float*)d_in[1];
    const float* W  = (const float*)d_in[2];
    const float* b  = (const float*)d_in[3];
    float* out = (float*)d_out;

    cudaFuncSetAttribute(fmu_kernel, cudaFuncAttributeMaxDynamicSharedMemorySize, SMEM_BYTES);
    cudaFuncSetAttribute(lse_mma_kernel, cudaFuncAttributeMaxDynamicSharedMemorySize, MMA_SMEM);

    fmu_kernel<<<dim3(M_ROWS / BM, D / BN), 256, SMEM_BYTES>>>(mu, W, b);
    rowsq_kernel<<<2048, 256>>>(x);
    lse_mma_kernel<<<dim3(N_ROWS / MMA_BM, NSLICE), 256, MMA_SMEM>>>();
    finalize_kernel<<<32, 256>>>();
    reduce_kernel<<<1, 256>>>(out);
}

// round 8
// speedup vs baseline: 4.8276x; 1.7411x over previous
#include <cuda_runtime.h>
#include <cuda_bf16.h>
#include <math.h>
#include <stdint.h>

#define N_ROWS 8192
#define M_ROWS 8192
#define D      512

// ------------------------- fmu mma kernel config ---------------------------
#define FM_BM 128
#define FM_BN 128
#define FM_KT 32
#define FM_PITCH 36                      // floats
#define FM_STAGEB ((FM_BM + FM_BN) * FM_PITCH * 4)  // 36864
#define FM_SMEM (2 * FM_STAGEB)
#define FM_NKST (D / FM_KT)              // 16

// ------------------------- bf16 LSE kernel config --------------------------
#define MMA_BM 128
#define MMA_BN 128
#define MMA_KT 32                        // K elems per stage
#define NSLICE 8
#define NCHUNK 8
#define NKST   (D / MMA_KT)              // 16
#define PITCH_H 40                       // smem pitch in halves (80 B)
#define ROW_B  (PITCH_H * 2)
#define STAGEB ((MMA_BM + MMA_BN) * ROW_B)   // 20480
#define MMA_SMEM (2 * STAGEB)                // 40960
#define NPART (NSLICE * 4)

// Scratch (device globals: no allocation allowed)
__device__ __nv_bfloat16 g_fb[M_ROWS * D];   // bf16(tanh(mu W^T + b))
__device__ __nv_bfloat16 g_xb[N_ROWS * D];   // bf16(x)
__device__ float g_fsq[M_ROWS];              // sum f~^2 (on bf16 values)
__device__ float g_xsq[N_ROWS];              // sum x^2 (exact)
__device__ float g_pmx[NPART * N_ROWS];
__device__ float g_ps [NPART * N_ROWS];
__device__ float g_lse[N_ROWS];

// ------------------------------ helpers ------------------------------------
__device__ __forceinline__ uint32_t smem_u32(const void* p) {
    uint32_t a;
    asm("{ .reg .u64 t; cvta.to.shared.u64 t, %1; cvt.u32.u64 %0, t; }" : "=r"(a) : "l"(p));
    return a;
}
__device__ __forceinline__ uint32_t bf2_as_u32(__nv_bfloat162 v) {
    union { __nv_bfloat162 h; uint32_t u; } c;
    c.h = v;
    return c.u;
}
__device__ __forceinline__ __nv_bfloat162 u32_as_bf2(uint32_t v) {
    union { uint32_t u; __nv_bfloat162 h; } c;
    c.u = v;
    return c.h;
}
__device__ __forceinline__ void cp16(uint32_t dst, const void* src) {
    asm volatile("cp.async.cg.shared.global [%0], [%1], 16;" :: "r"(dst), "l"(src) : "memory");
}
__device__ __forceinline__ void cp_commit() {
    asm volatile("cp.async.commit_group;" ::: "memory");
}
template <int N>
__device__ __forceinline__ void cp_wait() {
    asm volatile("cp.async.wait_group %0;" :: "n"(N) : "memory");
}
__device__ __forceinline__ void mma_tf32(float* c, const uint32_t* a, const uint32_t* b) {
    asm volatile(
        "mma.sync.aligned.m16n8k8.row.col.f32.tf32.tf32.f32 "
        "{%0,%1,%2,%3}, {%4,%5,%6,%7}, {%8,%9}, {%0,%1,%2,%3};"
        : "+f"(c[0]), "+f"(c[1]), "+f"(c[2]), "+f"(c[3])
        : "r"(a[0]), "r"(a[1]), "r"(a[2]), "r"(a[3]), "r"(b[0]), "r"(b[1]));
}
__device__ __forceinline__ void mma_bf16(float* c, const uint32_t* a, const uint32_t* b) {
    asm volatile(
        "mma.sync.aligned.m16n8k16.row.col.f32.bf16.bf16.f32 "
        "{%0,%1,%2,%3}, {%4,%5,%6,%7}, {%8,%9}, {%0,%1,%2,%3};"
        : "+f"(c[0]), "+f"(c[1]), "+f"(c[2]), "+f"(c[3])
        : "r"(a[0]), "r"(a[1]), "r"(a[2]), "r"(a[3]), "r"(b[0]), "r"(b[1]));
}

// ---------------------------------------------------------------------------
// Kernel 1: f_mu = tanh(mu @ W^T + b) via tf32 mma; stores bf16 to g_fb.
// grid (64, 4), block 256 (8 warps, 2 warprows x 4 warpcols)
// ---------------------------------------------------------------------------
__global__ __launch_bounds__(256)
void fmu_mma_kernel(const float* __restrict__ mu, const float* __restrict__ W,
                    const float* __restrict__ bias) {
    extern __shared__ char smraw[];
    const uint32_t smb = smem_u32(smraw);

    const int tid = threadIdx.x;
    const int wid = tid >> 5;
    const int lane = tid & 31;
    const int lr = lane >> 2, lc = lane & 3;
    const int warprow = wid >> 2, warpcol = wid & 3;

    const int row0 = blockIdx.x * FM_BM;
    const int colg0 = blockIdx.y * FM_BN;

    const char* gA0 = (const char*)mu + (size_t)row0 * (D * 4);
    const char* gB0 = (const char*)W + (size_t)colg0 * (D * 4);

    auto load_stage = [&](int s) {
        uint32_t bufA = smb + (s & 1) * FM_STAGEB;
        uint32_t bufB = bufA + FM_BM * (FM_PITCH * 4);
        const char* srcA = gA0 + (size_t)s * (FM_KT * 4);
        const char* srcB = gB0 + (size_t)s * (FM_KT * 4);
        #pragma unroll
        for (int q = 0; q < 4; ++q) {
            int idx = tid + q * 256;
            int row = idx >> 3, s8 = idx & 7;
            cp16(bufA + row * (FM_PITCH * 4) + s8 * 16, srcA + (size_t)row * (D * 4) + s8 * 16);
        }
        #pragma unroll
        for (int q = 0; q < 4; ++q) {
            int idx = tid + q * 256;
            int row = idx >> 3, s8 = idx & 7;
            cp16(bufB + row * (FM_PITCH * 4) + s8 * 16, srcB + (size_t)row * (D * 4) + s8 * 16);
        }
        cp_commit();
    };

    float acc[4][4][4];
    #pragma unroll
    for (int mt = 0; mt < 4; ++mt)
        #pragma unroll
        for (int nt = 0; nt < 4; ++nt)
            #pragma unroll
            for (int r = 0; r < 4; ++r) acc[mt][nt][r] = 0.f;

    load_stage(0);
    for (int s = 0; s < FM_NKST; ++s) {
        if (s + 1 < FM_NKST) { load_stage(s + 1); cp_wait<1>(); }
        else                 { cp_wait<0>(); }
        __syncthreads();

        const float* As = (const float*)(smraw + (s & 1) * FM_STAGEB);
        const float* Bs = As + FM_BM * FM_PITCH;

        #pragma unroll
        for (int k8 = 0; k8 < 4; ++k8) {
            const int kb = k8 * 8;
            uint32_t a[4][4], b[4][2];
            #pragma unroll
            for (int mt = 0; mt < 4; ++mt) {
                int r0 = warprow * 64 + mt * 16 + lr;
                a[mt][0] = __float_as_uint(As[(r0    ) * FM_PITCH + kb + lc    ]);
                a[mt][1] = __float_as_uint(As[(r0 + 8) * FM_PITCH + kb + lc    ]);
                a[mt][2] = __float_as_uint(As[(r0    ) * FM_PITCH + kb + lc + 4]);
                a[mt][3] = __float_as_uint(As[(r0 + 8) * FM_PITCH + kb + lc + 4]);
            }
            #pragma unroll
            for (int nt = 0; nt < 4; ++nt) {
                int c0 = warpcol * 32 + nt * 8 + lr;
                b[nt][0] = __float_as_uint(Bs[c0 * FM_PITCH + kb + lc    ]);
                b[nt][1] = __float_as_uint(Bs[c0 * FM_PITCH + kb + lc + 4]);
            }
            #pragma unroll
            for (int mt = 0; mt < 4; ++mt)
                #pragma unroll
                for (int nt = 0; nt < 4; ++nt)
                    mma_tf32(acc[mt][nt], a[mt], b[nt]);
        }
        __syncthreads();
    }

    // epilogue: tanh(acc + bias) -> bf16 g_fb
    #pragma unroll
    for (int nt = 0; nt < 4; ++nt) {
        int cg = colg0 + warpcol * 32 + nt * 8 + lc * 2;
        float b0 = __ldg(&bias[cg]), b1 = __ldg(&bias[cg + 1]);
        #pragma unroll
        for (int mt = 0; mt < 4; ++mt) {
            #pragma unroll
            for (int rh = 0; rh < 2; ++rh) {
                int row = row0 + warprow * 64 + mt * 16 + lr + rh * 8;
                float v0 = tanhf(acc[mt][nt][rh * 2]     + b0);
                float v1 = tanhf(acc[mt][nt][rh * 2 + 1] + b1);
                __nv_bfloat162 o = __float22bfloat162_rn(make_float2(v0, v1));
                *(__nv_bfloat162*)&g_fb[(size_t)row * D + cg] = o;
            }
        }
    }
}

// ---------------------------------------------------------------------------
// Kernel 2: g_xsq from exact x + bf16 copy of x into g_xb;
//           g_fsq from bf16 g_fb. one warp per row; 2048 blocks of 256.
// ---------------------------------------------------------------------------
__global__ void rowsq_kernel(const float* __restrict__ x) {
    int w = (blockIdx.x * blockDim.x + threadIdx.x) >> 5;
    int lane = threadIdx.x & 31;
    float s = 0.f;
    if (w < N_ROWS) {
        int row = w;
        const float4* p = (const float4*)(x + (size_t)row * D);
        uint2* q = (uint2*)(g_xb + (size_t)row * D);
        #pragma unroll
        for (int i = lane; i < D / 4; i += 32) {
            float4 v = p[i];
            s += v.x * v.x + v.y * v.y + v.z * v.z + v.w * v.w;
            uint2 o;
            o.x = bf2_as_u32(__float22bfloat162_rn(make_float2(v.x, v.y)));
            o.y = bf2_as_u32(__float22bfloat162_rn(make_float2(v.z, v.w)));
            q[i] = o;
        }
        #pragma unroll
        for (int off = 16; off; off >>= 1) s += __shfl_xor_sync(0xffffffffu, s, off);
        if (lane == 0) g_xsq[row] = s;
    } else {
        int row = w - N_ROWS;
        const uint2* p = (const uint2*)(g_fb + (size_t)row * D);
        #pragma unroll
        for (int i = lane; i < D / 4; i += 32) {
            uint2 v = p[i];
            float2 f0 = __bfloat1622float2(u32_as_bf2(v.x));
            float2 f1 = __bfloat1622float2(u32_as_bf2(v.y));
            s += f0.x * f0.x + f0.y * f0.y + f1.x * f1.x + f1.y * f1.y;
        }
        #pragma unroll
        for (int off = 16; off; off >>= 1) s += __shfl_xor_sync(0xffffffffu, s, off);
        if (lane == 0) g_fsq[row] = s;
    }
}

// ---------------------------------------------------------------------------
// Kernel 3: bf16 mma cross-GEMM fused with online logsumexp.
// grid (64 row-blocks, 8 M-slices), block 256 (2x4 warps), occupancy 2.
// CTA: 128 rows x 1024 cols (8 chunks of 128), K=512 in 16 stages of 32.
// ---------------------------------------------------------------------------
__global__ __launch_bounds__(256, 2)
void lse_mma_kernel() {
    extern __shared__ char smraw[];
    const uint32_t smb = smem_u32(smraw);

    const int tid = threadIdx.x;
    const int wid = tid >> 5;
    const int lane = tid & 31;
    const int lr = lane >> 2, lc = lane & 3;
    const int warprow = wid >> 2, warpcol = wid & 3;

    const int row0 = blockIdx.x * MMA_BM;
    const int slice = blockIdx.y;
    const int col_slice0 = slice * (MMA_BN * NCHUNK);

    const char* gA0 = (const char*)g_xb + (size_t)row0 * (D * 2);
    const char* gB0 = (const char*)g_fb + (size_t)col_slice0 * (D * 2);

    auto load_stage = [&](int s) {
        int kc = s & (NKST - 1);
        int ch = s >> 4;
        uint32_t bufA = smb + (s & 1) * STAGEB;
        uint32_t bufB = bufA + MMA_BM * ROW_B;
        const char* srcA = gA0 + (size_t)kc * (MMA_KT * 2);
        const char* srcB = gB0 + (size_t)ch * (MMA_BN * D * 2) + (size_t)kc * (MMA_KT * 2);
        #pragma unroll
        for (int q = 0; q < 2; ++q) {
            int idx = tid + q * 256;
            int row = idx >> 2, s8 = idx & 3;
            cp16(bufA + row * ROW_B + s8 * 16, srcA + (size_t)row * (D * 2) + s8 * 16);
        }
        #pragma unroll
        for (int q = 0; q < 2; ++q) {
            int idx = tid + q * 256;
            int row = idx >> 2, s8 = idx & 3;
            cp16(bufB + row * ROW_B + s8 * 16, srcB + (size_t)row * (D * 2) + s8 * 16);
        }
        cp_commit();
    };

    float acc[4][4][4];
    #pragma unroll
    for (int mt = 0; mt < 4; ++mt)
        #pragma unroll
        for (int nt = 0; nt < 4; ++nt)
            #pragma unroll
            for (int r = 0; r < 4; ++r) acc[mt][nt][r] = 0.f;

    float run_mx[8], run_s[8];
    #pragma unroll
    for (int i = 0; i < 8; ++i) { run_mx[i] = -INFINITY; run_s[i] = 0.f; }

    const int TOT = NCHUNK * NKST;   // 128
    load_stage(0);

    for (int s = 0; s < TOT; ++s) {
        if (s + 1 < TOT) { load_stage(s + 1); cp_wait<1>(); }
        else             { cp_wait<0>(); }
        __syncthreads();

        const uint16_t* As = (const uint16_t*)(smraw + (s & 1) * STAGEB);
        const uint16_t* Bs = As + MMA_BM * PITCH_H;

        #pragma unroll
        for (int k16 = 0; k16 < 2; ++k16) {
            const int kb = k16 * 16;
            uint32_t a[4][4], b[4][2];
            #pragma unroll
            for (int mt = 0; mt < 4; ++mt) {
                int r0 = warprow * 64 + mt * 16 + lr;
                a[mt][0] = *(const uint32_t*)&As[(r0    ) * PITCH_H + kb + 2 * lc    ];
                a[mt][1] = *(const uint32_t*)&As[(r0 + 8) * PITCH_H + kb + 2 * lc    ];
                a[mt][2] = *(const uint32_t*)&As[(r0    ) * PITCH_H + kb + 2 * lc + 8];
                a[mt][3] = *(const uint32_t*)&As[(r0 + 8) * PITCH_H + kb + 2 * lc + 8];
            }
            #pragma unroll
            for (int nt = 0; nt < 4; ++nt) {
                int c0 = warpcol * 32 + nt * 8 + lr;
                b[nt][0] = *(const uint32_t*)&Bs[c0 * PITCH_H + kb + 2 * lc    ];
                b[nt][1] = *(const uint32_t*)&Bs[c0 * PITCH_H + kb + 2 * lc + 8];
            }
            #pragma unroll
            for (int mt = 0; mt < 4; ++mt)
                #pragma unroll
                for (int nt = 0; nt < 4; ++nt)
                    mma_bf16(acc[mt][nt], a[mt], b[nt]);
        }

        if ((s & (NKST - 1)) == NKST - 1) {
            int ch = s >> 4;
            const int colg0 = col_slice0 + ch * MMA_BN + warpcol * 32;
            float fq[4][2];
            #pragma unroll
            for (int nt = 0; nt < 4; ++nt) {
                int cg = colg0 + nt * 8 + lc * 2;
                fq[nt][0] = __ldg(&g_fsq[cg]);
                fq[nt][1] = __ldg(&g_fsq[cg + 1]);
            }
            #pragma unroll
            for (int mt = 0; mt < 4; ++mt) {
                #pragma unroll
                for (int rh = 0; rh < 2; ++rh) {
                    const int si = mt * 2 + rh;
                    float mv[8];
                    #pragma unroll
                    for (int nt = 0; nt < 4; ++nt) {
                        mv[2 * nt]     = acc[mt][nt][rh * 2]     - 0.5f * fq[nt][0];
                        mv[2 * nt + 1] = acc[mt][nt][rh * 2 + 1] - 0.5f * fq[nt][1];
                    }
                    float tm = mv[0];
                    #pragma unroll
                    for (int j = 1; j < 8; ++j) tm = fmaxf(tm, mv[j]);
                    float nm = fmaxf(run_mx[si], tm);
                    float ss = 0.f;
                    #pragma unroll
                    for (int j = 0; j < 8; ++j) ss += __expf(mv[j] - nm);
                    run_s[si] = run_s[si] * __expf(run_mx[si] - nm) + ss;
                    run_mx[si] = nm;
                }
            }
            #pragma unroll
            for (int mt = 0; mt < 4; ++mt)
                #pragma unroll
                for (int nt = 0; nt < 4; ++nt)
                    #pragma unroll
                    for (int r = 0; r < 4; ++r) acc[mt][nt][r] = 0.f;
        }
        __syncthreads();
    }

    // merge (mx,s) across the 4 lanes of each quad (same row, different cols)
    #pragma unroll
    for (int i = 0; i < 8; ++i) {
        float mx = run_mx[i], ss = run_s[i];
        #pragma unroll
        for (int off = 1; off <= 2; off <<= 1) {
            float omx = __shfl_xor_sync(0xffffffffu, mx, off);
            float os  = __shfl_xor_sync(0xffffffffu, ss, off);
            float nm = fmaxf(mx, omx);
            ss = ss * __expf(mx - nm) + os * __expf(omx - nm);
            mx = nm;
        }
        if (lc == 0) {
            int row = row0 + warprow * 64 + (i >> 1) * 16 + lr + (i & 1) * 8;
            int p = slice * 4 + warpcol;
            g_pmx[(size_t)p * N_ROWS + row] = mx;
            g_ps [(size_t)p * N_ROWS + row] = ss;
        }
    }
}

// ---------------------------------------------------------------------------
// Kernel 4: merge NPART partials per row -> g_lse. grid 32 x 256.
// ---------------------------------------------------------------------------
__global__ void finalize_kernel() {
    int row = blockIdx.x * blockDim.x + threadIdx.x;
    float mx = -INFINITY, s = 0.f;
    #pragma unroll 4
    for (int p = 0; p < NPART; ++p) {
        float omx = g_pmx[(size_t)p * N_ROWS + row];
        float os  = g_ps [(size_t)p * N_ROWS + row];
        float nm = fmaxf(mx, omx);
        s = s * __expf(mx - nm) + os * __expf(omx - nm);
        mx = nm;
    }
    g_lse[row] = mx + __logf(s) - 0.5f * g_xsq[row];
}

// ---------------------------------------------------------------------------
// Kernel 5: out = -sum(g_lse)  (deterministic tree reduction)
// ---------------------------------------------------------------------------
__global__ void reduce_kernel(float* __restrict__ out) {
    __shared__ float sh[256];
    float s = 0.f;
    for (int i = threadIdx.x; i < N_ROWS; i += 256) s += g_lse[i];
    sh[threadIdx.x] = s;
    __syncthreads();
    for (int st = 128; st; st >>= 1) {
        if (threadIdx.x < st) sh[threadIdx.x] += sh[threadIdx.x + st];
        __syncthreads();
    }
    if (threadIdx.x == 0) out[0] = -sh[0];
}

extern "C" void kernel_launch(void* const* d_in, const int* in_sizes, int n_in,
                              void* d_out, int out_size) {
    const float* x  = (const float*)d_in[0];
    const float* mu = (const float*)d_in[1];
    const float* W  = (const float*)d_in[2];
    const float* b  = (const float*)d_in[3];
    float* out = (float*)d_out;

    cudaFuncSetAttribute(fmu_mma_kernel, cudaFuncAttributeMaxDynamicSharedMemorySize, FM_SMEM);
    cudaFuncSetAttribute(lse_mma_kernel, cudaFuncAttributeMaxDynamicSharedMemorySize, MMA_SMEM);

    fmu_mma_kernel<<<dim3(M_ROWS / FM_BM, D / FM_BN), 256, FM_SMEM>>>(mu, W, b);
    rowsq_kernel<<<2048, 256>>>(x);
    lse_mma_kernel<<<dim3(N_ROWS / MMA_BM, NSLICE), 256, MMA_SMEM>>>();
    finalize_kernel<<<32, 256>>>();
    reduce_kernel<<<1, 256>>>(out);
}